// round 13
// baseline (speedup 1.0000x reference)
#include <cuda_runtime.h>
#include <cstdint>

#define N_NODES 10000
#define E_TOTAL 640000
#define D_NODE 128
#define D_EDGE 64
#define D_IN 192
#define D_OUT 128

#define TM 128              // edges per CTA
#define NTHREADS 256        // 8 warps
#define KCH 96              // K chunk
#define A_STRIDE 100        // mod 32 = 4 -> conflict-free A frags
#define W_STRIDE 136        // mod 32 = 8 -> conflict-free B frags
#define EP_STRIDE 132       // epilogue repack stride (words)

#define SMEM_A_WORDS (TM * A_STRIDE)            // 12800
#define SMEM_W_WORDS (KCH * W_STRIDE)           // 13056
#define SMEM_BYTES ((SMEM_A_WORDS + SMEM_W_WORDS) * 4)   // 103424 -> 2 CTAs/SM

__device__ float g_cnt[N_NODES];
__device__ int   g_idx64;

__device__ __forceinline__ uint32_t f2tf32(float f) {
    uint32_t u;
    asm("cvt.rna.tf32.f32 %0, %1;" : "=r"(u) : "f"(f));
    return u;
}
__device__ __forceinline__ void mma_tf32(float* d, const uint32_t* a,
                                         uint32_t b0, uint32_t b1) {
    asm volatile(
        "mma.sync.aligned.m16n8k8.row.col.f32.tf32.tf32.f32 "
        "{%0,%1,%2,%3}, {%4,%5,%6,%7}, {%8,%9}, {%0,%1,%2,%3};"
        : "+f"(d[0]), "+f"(d[1]), "+f"(d[2]), "+f"(d[3])
        : "r"(a[0]), "r"(a[1]), "r"(a[2]), "r"(a[3]), "r"(b0), "r"(b1));
}
__device__ __forceinline__ void redv4(float* p, float a, float b, float c, float d) {
    asm volatile("red.global.add.v4.f32 [%0], {%1, %2, %3, %4};"
                 :: "l"(p), "f"(a), "f"(b), "f"(c), "f"(d) : "memory");
}
__device__ __forceinline__ int clampi(int v, int lo, int hi) {
    return v < lo ? lo : (v > hi ? hi : v);
}

// -------------------------------------------------------------------------
__global__ void zero_kernel(float* __restrict__ out, const unsigned* __restrict__ eiw) {
    int i = blockIdx.x * blockDim.x + threadIdx.x;
    if (i < N_NODES * D_OUT) out[i] = 0.0f;
    if (i < N_NODES) g_cnt[i] = 0.0f;
    if (blockIdx.x == 0 && threadIdx.x == 0) {
        int is64 = 1;
        #pragma unroll 1
        for (int k = 0; k < 64; k++) {
            unsigned hi = eiw[2 * k + 1];
            if (hi != 0u && hi != 0xFFFFFFFFu) { is64 = 0; break; }
        }
        g_idx64 = is64;
    }
}

// -------------------------------------------------------------------------
// Fused gather + tf32 mma.sync GEMM + smem-repacked v4 scatter-add.
// CTA: 128 edges x 128 cols, K = 2 chunks of 96.
// Warp w: rows (w>>1)*32 .. +31, cols (w&1)*64 .. +63.
// -------------------------------------------------------------------------
extern __shared__ uint32_t dsm[];

__global__ void __launch_bounds__(NTHREADS, 2)
gemm_scatter_mma(const float* __restrict__ x,
                 const void* __restrict__ ei_raw,
                 const float* __restrict__ ef,
                 const float* __restrict__ W,
                 float* __restrict__ out)
{
    __shared__ int s_src[TM];
    __shared__ int s_dst[TM];

    uint32_t* sA = dsm;                      // [TM][A_STRIDE]
    uint32_t* sW = dsm + SMEM_A_WORDS;       // [KCH][W_STRIDE]
    float*    sE = (float*)dsm;              // epilogue repack [TM][EP_STRIDE]

    const int tid = threadIdx.x;
    const int wid = tid >> 5;
    const int lane = tid & 31;
    const int e0 = blockIdx.x * TM;

    if (tid < TM) {
        int s, d;
        if (g_idx64) {
            const long long* ei = (const long long*)ei_raw;
            s = (int)ei[e0 + tid];
            d = (int)ei[E_TOTAL + e0 + tid];
        } else {
            const int* ei = (const int*)ei_raw;
            s = ei[e0 + tid];
            d = ei[E_TOTAL + e0 + tid];
        }
        s_src[tid] = clampi(s, 0, N_NODES - 1);
        s_dst[tid] = clampi(d, 0, N_NODES - 1);
        atomicAdd(&g_cnt[s_dst[tid]], 1.0f);
    }

    const int rowband = (wid >> 1) * 32;
    const int colh = (wid & 1) * 64;
    const int lq = lane >> 2;      // 0..7
    const int lr = lane & 3;       // 0..3

    float acc[2][8][4];
#pragma unroll
    for (int m = 0; m < 2; m++)
#pragma unroll
        for (int nt = 0; nt < 8; nt++)
#pragma unroll
            for (int c = 0; c < 4; c++) acc[m][nt][c] = 0.0f;

#pragma unroll 1
    for (int ch = 0; ch < 2; ch++) {
        __syncthreads();   // smem free (also orders s_src on first pass)

        // ---- stage A chunk: 128 rows x 96 cols (24 float4 per row) ----
        #pragma unroll 2
        for (int idx = tid; idx < TM * 24; idx += NTHREADS) {
            int e = idx / 24, q = idx - e * 24;
            float4 v;
            if (ch == 0) {
                v = ((const float4*)(x + (size_t)s_src[e] * D_NODE))[q];
            } else {
                if (q < 8) v = ((const float4*)(x + (size_t)s_src[e] * D_NODE))[24 + q];
                else       v = ((const float4*)(ef + (size_t)(e0 + e) * D_EDGE))[q - 8];
            }
            uint4 t;
            t.x = f2tf32(v.x); t.y = f2tf32(v.y);
            t.z = f2tf32(v.z); t.w = f2tf32(v.w);
            *(uint4*)(sA + e * A_STRIDE + q * 4) = t;
        }
        // ---- stage W chunk: 96 rows x 128 cols ----
        #pragma unroll 2
        for (int idx = tid; idx < KCH * 32; idx += NTHREADS) {
            int k = idx >> 5, nq = idx & 31;
            float4 v = ((const float4*)(W + (size_t)(ch * KCH + k) * D_OUT))[nq];
            uint4 t;
            t.x = f2tf32(v.x); t.y = f2tf32(v.y);
            t.z = f2tf32(v.z); t.w = f2tf32(v.w);
            *(uint4*)(sW + k * W_STRIDE + nq * 4) = t;
        }
        __syncthreads();

        // ---- 12 k-steps of m16n8k8 ----
#pragma unroll
        for (int s = 0; s < KCH / 8; s++) {
            const int kb = s * 8;
            uint32_t a[2][4];
            {
                const uint32_t* pa = sA + (rowband + lq) * A_STRIDE + kb + lr;
                a[0][0] = pa[0];
                a[0][1] = pa[8 * A_STRIDE];
                a[0][2] = pa[4];
                a[0][3] = pa[8 * A_STRIDE + 4];
                a[1][0] = pa[16 * A_STRIDE];
                a[1][1] = pa[24 * A_STRIDE];
                a[1][2] = pa[16 * A_STRIDE + 4];
                a[1][3] = pa[24 * A_STRIDE + 4];
            }
            const uint32_t* pb0 = sW + (kb + lr) * W_STRIDE + colh + lq;
            const uint32_t* pb1 = pb0 + 4 * W_STRIDE;
#pragma unroll
            for (int nt = 0; nt < 8; nt++) {
                uint32_t b0 = pb0[nt * 8];
                uint32_t b1 = pb1[nt * 8];
                mma_tf32(acc[0][nt], a[0], b0, b1);
                mma_tf32(acc[1][nt], a[1], b0, b1);
            }
        }
    }

    // ---- epilogue: repack accumulators through smem, then v4 scatter ----
    __syncthreads();   // all compute done; safe to overwrite sA/sW
#pragma unroll
    for (int m = 0; m < 2; m++) {
        int r = rowband + m * 16 + lq;
        int cb = colh + 2 * lr;
#pragma unroll
        for (int nt = 0; nt < 8; nt++) {
            sE[r * EP_STRIDE + cb + nt * 8]           = acc[m][nt][0];
            sE[r * EP_STRIDE + cb + nt * 8 + 1]       = acc[m][nt][1];
            sE[(r + 8) * EP_STRIDE + cb + nt * 8]     = acc[m][nt][2];
            sE[(r + 8) * EP_STRIDE + cb + nt * 8 + 1] = acc[m][nt][3];
        }
    }
    __syncthreads();

    {
        const int row = tid >> 1;            // 0..127
        const int h   = tid & 1;             // column half
        const float* se = sE + row * EP_STRIDE + h * 64;
        float* po = out + (size_t)s_dst[row] * D_OUT + h * 64;
#pragma unroll
        for (int i = 0; i < 16; i++) {
            float4 v = *(const float4*)(se + i * 4);
            redv4(po + i * 4, v.x, v.y, v.z, v.w);
        }
    }
}

// -------------------------------------------------------------------------
__global__ void finalize_kernel(float* __restrict__ out, const float* __restrict__ b) {
    int i = blockIdx.x * blockDim.x + threadIdx.x;
    if (i >= N_NODES * D_OUT) return;
    int node = i >> 7;
    float c = g_cnt[node];
    float v = out[i];
    out[i] = (c > 0.0f) ? (v / c + b[i & (D_OUT - 1)]) : 0.0f;
}

// -------------------------------------------------------------------------
extern "C" void kernel_launch(void* const* d_in, const int* in_sizes, int n_in,
                              void* d_out, int out_size)
{
    const float* x  = (const float*)d_in[0];
    const void*  ei = d_in[1];
    const float* ef = (const float*)d_in[2];
    const float* W  = (const float*)d_in[3];
    const float* b  = (const float*)d_in[4];
    float* out = (float*)d_out;

    cudaFuncSetAttribute(gemm_scatter_mma,
                         cudaFuncAttributeMaxDynamicSharedMemorySize, SMEM_BYTES);

    const int total = N_NODES * D_OUT;
    zero_kernel<<<(total + 255) / 256, 256>>>(out, (const unsigned*)ei);
    gemm_scatter_mma<<<E_TOTAL / TM, NTHREADS, SMEM_BYTES>>>(x, ei, ef, W, out);
    finalize_kernel<<<(total + 255) / 256, 256>>>(out, b);
}